// round 17
// baseline (speedup 1.0000x reference)
#include <cuda_runtime.h>
#include <cuda_fp16.h>
#include <math.h>
#include <stdint.h>

#define T_SEQ 2048
#define DIM   4096
#define NH    32
#define NKV   8
#define HD    128
#define KVD   1024
#define KDIM  4096

// ---------------- scratch (static __device__, no allocation) ----------------
__device__ __half g_xh [T_SEQ * DIM];
__device__ __half g_woh[DIM * DIM];
__device__ __half g_wkh[KVD * DIM];
__device__ __half g_wvh[KVD * DIM];
__device__ __half g_qh [T_SEQ * DIM];
__device__ __half g_kh [T_SEQ * KVD];
__device__ __half g_vh [T_SEQ * KVD];
__device__ __half g_ah [T_SEQ * DIM];

// ---------------- PTX helpers (baseline ISA only) ----------------
__device__ __forceinline__ uint32_t smem_u32(const void* p) {
    uint32_t a;
    asm("{ .reg .u64 t; cvta.to.shared.u64 t, %1; cvt.u32.u64 %0, t; }" : "=r"(a) : "l"(p));
    return a;
}
#define CP16(dst, src) asm volatile("cp.async.cg.shared.global [%0], [%1], 16;" :: "r"(dst), "l"(src))
#define CP_COMMIT()    asm volatile("cp.async.commit_group;" ::: "memory")
#define CP_WAIT0()     asm volatile("cp.async.wait_group 0;" ::: "memory")

#define LDSM4(r, a) asm volatile( \
    "ldmatrix.sync.aligned.m8n8.x4.shared.b16 {%0,%1,%2,%3}, [%4];" \
    : "=r"((r)[0]), "=r"((r)[1]), "=r"((r)[2]), "=r"((r)[3]) : "r"(a))
#define LDSM4T(r, a) asm volatile( \
    "ldmatrix.sync.aligned.m8n8.x4.trans.shared.b16 {%0,%1,%2,%3}, [%4];" \
    : "=r"((r)[0]), "=r"((r)[1]), "=r"((r)[2]), "=r"((r)[3]) : "r"(a))

#define MMAH(c, a, b0, b1) asm volatile( \
    "mma.sync.aligned.m16n8k16.row.col.f32.f16.f16.f32 " \
    "{%0,%1,%2,%3},{%4,%5,%6,%7},{%8,%9},{%0,%1,%2,%3};" \
    : "+f"((c)[0]), "+f"((c)[1]), "+f"((c)[2]), "+f"((c)[3]) \
    : "r"((a)[0]), "r"((a)[1]), "r"((a)[2]), "r"((a)[3]), "r"(b0), "r"(b1))

__device__ __forceinline__ uint32_t packh2(float x, float y) {
    __half2 h = __floats2half2_rn(x, y);
    return *(uint32_t*)&h;
}

// ---------------------------------------------------------------------------
// merged fp32 -> fp16 convert, 8 independent float4 per thread (MLP=8)
// region boundaries (2M/6M/7M/8M f4) are multiples of 8 -> no straddle
// ---------------------------------------------------------------------------
__global__ __launch_bounds__(256) void cvt_all_kernel(
    const float* __restrict__ x,  const float* __restrict__ wo,
    const float* __restrict__ wk, const float* __restrict__ wv,
    __half* __restrict__ xh,  __half* __restrict__ woh,
    __half* __restrict__ wkh, __half* __restrict__ wvh)
{
    const long i = (long)blockIdx.x * blockDim.x + threadIdx.x;
    const long j = i * 8;
    const float4* s; __half2* d; long base;
    if (j < 2L*1024*1024)      { s = (const float4*)x;  d = (__half2*)xh;  base = j; }
    else if (j < 6L*1024*1024) { s = (const float4*)wo; d = (__half2*)woh; base = j - 2L*1024*1024; }
    else if (j < 7L*1024*1024) { s = (const float4*)wk; d = (__half2*)wkh; base = j - 6L*1024*1024; }
    else                       { s = (const float4*)wv; d = (__half2*)wvh; base = j - 7L*1024*1024; }
    float4 v[8];
    #pragma unroll
    for (int t = 0; t < 8; t++) v[t] = s[base + t];
    #pragma unroll
    for (int t = 0; t < 8; t++) {
        d[(base + t) * 2]     = __floats2half2_rn(v[t].x, v[t].y);
        d[(base + t) * 2 + 1] = __floats2half2_rn(v[t].z, v[t].w);
    }
}

// ---------------------------------------------------------------------------
// fp16 tensor-core GEMM core — BYTE-IDENTICAL to the passing R11/R15 version.
// ---------------------------------------------------------------------------
#define ROWB   144u                  // 128B data + 16B pad
#define B_OFF  (128u * 144u)
#define STAGEB (2u * 128u * 144u)
#define GSMEM  (2 * 36864)

template<bool ROPE, bool F32OUT>
__device__ __forceinline__ void gemm_core(
    const __half* __restrict__ A, const __half* __restrict__ W,
    const float* __restrict__ bias,
    float* __restrict__ Cout, __half* __restrict__ Ch,
    const float* __restrict__ fc, const float* __restrict__ fs,
    int bm, int n0, int ldc, uint32_t sb)
{
    const int tid  = threadIdx.x;
    const int lane = tid & 31;
    const int wid  = tid >> 5;
    const int wm   = wid & 1;
    const int wn   = wid >> 1;

    // cp.async geometry: thread covers rows {r0, r0+32, r0+64, r0+96}, 16B col cc
    const int r0 = tid >> 3, cc = tid & 7;
    const uint32_t so = (uint32_t)r0 * ROWB + cc * 16u;
    const size_t  go = (size_t)r0 * 8192 + cc * 16;

    const char* pA = (const char*)A + (size_t)bm * 8192;
    const char* pB = (const char*)W + (size_t)n0 * 8192;

    float acc[4][4][4];
    #pragma unroll
    for (int i = 0; i < 4; i++)
        #pragma unroll
        for (int j = 0; j < 4; j++)
            #pragma unroll
            for (int t = 0; t < 4; t++) acc[i][j][t] = 0.f;

    const int NC = KDIM / 64;   // 64 chunks

    // prologue: chunk 0 (burst; nothing to overlap with)
    {
        #pragma unroll
        for (int p = 0; p < 4; p++) {
            CP16(sb + so + p * (32u * ROWB),         pA + go + (size_t)p * (32 * 8192));
            CP16(sb + B_OFF + so + p * (32u * ROWB), pB + go + (size_t)p * (32 * 8192));
        }
        CP_COMMIT();
    }

    const uint32_t aRow = (uint32_t)(wm * 64 + (lane & 15)) * ROWB + ((lane >> 4) & 1) * 16u;
    const uint32_t bRow = (uint32_t)(wn * 32 + ((lane >> 4) << 3) + (lane & 7)) * ROWB
                        + ((lane >> 3) & 1) * 16u;

    for (int c = 0; c < NC; ++c) {
        CP_WAIT0();                       // chunk c resident
        __syncthreads();                  // stage (c-1)&1 free, chunk c visible

        const uint32_t stg = sb + (uint32_t)(c & 1) * STAGEB;
        const bool more = (c + 1 < NC);
        const uint32_t nst = sb + (uint32_t)((c + 1) & 1) * STAGEB;
        const size_t  nkb = (size_t)(c + 1) * 128;

        #pragma unroll
        for (int k16 = 0; k16 < 4; ++k16) {
            // interleave 2 of the 8 next-chunk cp.async into this k16 slot
            if (more) {
                CP16(nst + so + (uint32_t)k16 * (32u * ROWB),
                     pA + go + (size_t)k16 * (32 * 8192) + nkb);
                CP16(nst + B_OFF + so + (uint32_t)k16 * (32u * ROWB),
                     pB + go + (size_t)k16 * (32 * 8192) + nkb);
            }
            const uint32_t kb = (uint32_t)k16 * 32u;
            uint32_t ah[4][4], bh[2][4];
            #pragma unroll
            for (int i = 0; i < 4; i++)
                LDSM4(ah[i], stg + aRow + (uint32_t)(i * 16) * ROWB + kb);
            #pragma unroll
            for (int p = 0; p < 2; p++)
                LDSM4(bh[p], stg + B_OFF + bRow + (uint32_t)(p * 16) * ROWB + kb);
            #pragma unroll
            for (int i = 0; i < 4; i++) {
                #pragma unroll
                for (int j = 0; j < 4; j++) {
                    const int p = j >> 1, f = (j & 1) * 2;
                    MMAH(acc[i][j], ah[i], bh[p][f], bh[p][f + 1]);
                }
            }
        }
        if (more) CP_COMMIT();
    }

    // ---- epilogue ----
    #pragma unroll
    for (int i = 0; i < 4; i++) {
        const int row0 = bm + wm * 64 + i * 16 + (lane >> 2);
        #pragma unroll
        for (int j = 0; j < 4; j++) {
            const int col = n0 + wn * 32 + j * 8 + (lane & 3) * 2;
            const float bv0 = bias[col], bv1 = bias[col + 1];
            #pragma unroll
            for (int t = 0; t < 2; t++) {
                const int row = row0 + t * 8;
                float v0 = acc[i][j][2 * t]     + bv0;
                float v1 = acc[i][j][2 * t + 1] + bv1;
                if (F32OUT) {
                    *(float2*)&Cout[(size_t)row * ldc + col] = make_float2(v0, v1);
                } else {
                    if (ROPE) {
                        const int idx = (col & (HD - 1)) >> 1;
                        const float cs = fc[row * 64 + idx];
                        const float sn = fs[row * 64 + idx];
                        const float re = v0 * cs - v1 * sn;
                        const float im = v0 * sn + v1 * cs;
                        v0 = re; v1 = im;
                    }
                    *(uint32_t*)&Ch[(size_t)row * ldc + col] = packh2(v0, v1);
                }
            }
        }
    }
}

// QKV: grid (48, 16), BN=128. bx<32: q (RoPE); [32,40): k (RoPE); [40,48): v.
__global__ __launch_bounds__(256, 2) void qkv_gemm_kernel(
    const __half* __restrict__ A,
    const __half* __restrict__ Wq, const float* __restrict__ bq, __half* __restrict__ Cq,
    const __half* __restrict__ Wk, const float* __restrict__ bk, __half* __restrict__ Ck,
    const __half* __restrict__ Wv, const float* __restrict__ bv, __half* __restrict__ Cv,
    const float* __restrict__ fc, const float* __restrict__ fs)
{
    extern __shared__ char dsm[];
    const uint32_t sb = smem_u32(dsm);
    const int bx = blockIdx.x;
    const int bm = blockIdx.y * 128;
    if (bx < 32) {
        gemm_core<true, false>(A, Wq, bq, nullptr, Cq, fc, fs, bm, bx * 128, DIM, sb);
    } else if (bx < 40) {
        gemm_core<true, false>(A, Wk, bk, nullptr, Ck, fc, fs, bm, (bx - 32) * 128, KVD, sb);
    } else {
        gemm_core<false, false>(A, Wv, bv, nullptr, Cv, fc, fs, bm, (bx - 40) * 128, KVD, sb);
    }
}

// Out-proj: grid (32, 16), BN=128, fp32 output.
__global__ __launch_bounds__(256, 2) void out_gemm_kernel(
    const __half* __restrict__ A,
    const __half* __restrict__ W, const float* __restrict__ bias,
    float* __restrict__ Cout)
{
    extern __shared__ char dsm[];
    const uint32_t sb = smem_u32(dsm);
    gemm_core<false, true>(A, W, bias, Cout, nullptr, nullptr, nullptr,
                           blockIdx.y * 128, blockIdx.x * 128, DIM, sb);
}

// ---------------------------------------------------------------------------
// fp16 tensor-core flash attention (fp32 softmax), causal, GQA.
// R11 pipeline choreography; per-tile Q LDSM (no hoist) to fit 128 regs;
// __launch_bounds__(256,2) -> 2 CTAs/SM (2 x 104448B smem = 208896 fits);
// fully-masked warps skip compute on the final tile (loads preserved).
// ---------------------------------------------------------------------------
#define FROWB  272u
#define SQ_    0u
#define SKV    34816u
#define VOFF   17408u
#define KVSTG  34816u
#define FA2SMEM (34816 + 2 * 34816)

__global__ __launch_bounds__(256, 2) void fa_mma_kernel(
    const __half* __restrict__ qh, const __half* __restrict__ kh,
    const __half* __restrict__ vh, __half* __restrict__ oh)
{
    extern __shared__ char sm[];
    const uint32_t sb = smem_u32(sm);

    const int qtile = gridDim.x - 1 - blockIdx.x;
    const int h = blockIdx.y, kvh = h >> 2;
    const int tid = threadIdx.x, wid = tid >> 5, lane = tid & 31;
    const int qbase = qtile * 128;

    // per-part KV load geometry: part p covers rows (tid>>4)+16p, col (tid&15)*16
    const uint32_t kvr = (uint32_t)(tid >> 4);
    const uint32_t kvc = (uint32_t)(tid & 15) * 16u;
    const uint32_t kvd0 = kvr * FROWB + kvc;
    const size_t   kvg0 = (size_t)kvr * 2048 + kvc;

    {   // Q tile load (prologue burst)
        const char* gq = (const char*)qh + ((size_t)qbase * DIM + h * HD) * 2;
        for (int i = tid; i < 2048; i += 256) {
            uint32_t r = i >> 4, c = i & 15;
            CP16(sb + SQ_ + r * FROWB + c * 16, gq + (size_t)r * 8192 + c * 16);
        }
    }
    {   // KV tile 0 (prologue burst)
        size_t gb = ((size_t)0 * KVD + kvh * HD) * 2;
        #pragma unroll
        for (int p = 0; p < 4; p++) {
            uint32_t d = sb + SKV + kvd0 + (uint32_t)p * (16u * FROWB);
            size_t   s2 = gb + kvg0 + (size_t)p * (16 * 2048);
            CP16(d,        (const char*)kh + s2);
            CP16(d + VOFF, (const char*)vh + s2);
        }
        CP_COMMIT();
    }

    const int NT = (qtile + 1) * 2;

    float m0 = -1e30f, m1 = -1e30f, l0 = 0.f, l1 = 0.f;
    float acc_o[16][4];
    #pragma unroll
    for (int n = 0; n < 16; n++)
        #pragma unroll
        for (int t = 0; t < 4; t++) acc_o[n][t] = 0.f;

    const float kl = 0.12751689f;  // (1/sqrt(128)) * log2(e)
    const uint32_t aoff = (uint32_t)(wid * 16 + (lane & 15)) * FROWB + (uint32_t)((lane >> 4) & 1) * 16u;
    const uint32_t boffBase = (uint32_t)(((lane >> 4) << 3) + (lane & 7)) * FROWB
                            + (uint32_t)((lane >> 3) & 1) * 16u;
    const uint32_t voffBase = (uint32_t)(lane & 15) * FROWB + (uint32_t)(lane >> 4) * 16u;
    const int r0g = qbase + wid * 16 + (lane >> 2);
    const int rmax = qbase + wid * 16 + 15;          // last row this warp owns

    for (int c = 0; c < NT; ++c) {
        CP_WAIT0();
        __syncthreads();

        const uint32_t stg = sb + SKV + (uint32_t)(c & 1) * KVSTG;
        const bool more = (c + 1 < NT);
        const uint32_t nst = sb + SKV + (uint32_t)((c + 1) & 1) * KVSTG;
        const size_t  ngb = ((size_t)(c + 1) * 64 * KVD + kvh * HD) * 2;

        const int jbase = c * 64;
        const bool skip = (jbase > rmax);             // tile fully masked for warp

        float s[8][4];

        if (skip) {
            // still perform this thread's share of next-tile loads
            if (more) {
                #pragma unroll
                for (int p = 0; p < 4; p++) {
                    uint32_t d = nst + kvd0 + (uint32_t)p * (16u * FROWB);
                    size_t   s2 = ngb + kvg0 + (size_t)p * (16 * 2048);
                    CP16(d,        (const char*)kh + s2);
                    CP16(d + VOFF, (const char*)vh + s2);
                }
            }
        } else {
            #pragma unroll
            for (int j = 0; j < 8; j++)
                #pragma unroll
                for (int t = 0; t < 4; t++) s[j][t] = 0.f;

            #pragma unroll
            for (int kk = 0; kk < 8; ++kk) {
                if ((kk & 1) == 0 && more) {
                    const int p = kk >> 1;
                    uint32_t d = nst + kvd0 + (uint32_t)p * (16u * FROWB);
                    size_t   s2 = ngb + kvg0 + (size_t)p * (16 * 2048);
                    CP16(d,        (const char*)kh + s2);
                    CP16(d + VOFF, (const char*)vh + s2);
                }
                uint32_t ah[4];
                LDSM4(ah, sb + SQ_ + aoff + kk * 32);
                #pragma unroll
                for (int g = 0; g < 4; ++g) {
                    uint32_t bh[4];
                    LDSM4(bh, stg + (uint32_t)(g * 16) * FROWB + boffBase + kk * 32);
                    MMAH(s[2*g],   ah, bh[0], bh[1]);
                    MMAH(s[2*g+1], ah, bh[2], bh[3]);
                }
            }
        }
        if (more) CP_COMMIT();

        if (!skip) {
            if (jbase + 63 > qbase + wid * 16) {
                #pragma unroll
                for (int j = 0; j < 8; j++) {
                    int col = jbase + j * 8 + (lane & 3) * 2;
                    if (col     > r0g)     s[j][0] = -1e30f;
                    if (col + 1 > r0g)     s[j][1] = -1e30f;
                    if (col     > r0g + 8) s[j][2] = -1e30f;
                    if (col + 1 > r0g + 8) s[j][3] = -1e30f;
                }
            }

            float mx0 = -1e30f, mx1 = -1e30f;
            #pragma unroll
            for (int j = 0; j < 8; j++) {
                mx0 = fmaxf(mx0, fmaxf(s[j][0], s[j][1]));
                mx1 = fmaxf(mx1, fmaxf(s[j][2], s[j][3]));
            }
            mx0 = fmaxf(mx0, __shfl_xor_sync(0xFFFFFFFFu, mx0, 1));
            mx0 = fmaxf(mx0, __shfl_xor_sync(0xFFFFFFFFu, mx0, 2));
            mx1 = fmaxf(mx1, __shfl_xor_sync(0xFFFFFFFFu, mx1, 1));
            mx1 = fmaxf(mx1, __shfl_xor_sync(0xFFFFFFFFu, mx1, 2));
            const float nm0 = fmaxf(m0, mx0), nm1 = fmaxf(m1, mx1);
            const float corr0 = exp2f((m0 - nm0) * kl), corr1 = exp2f((m1 - nm1) * kl);
            const float nb0 = -nm0 * kl, nb1 = -nm1 * kl;
            float sum0 = 0.f, sum1 = 0.f;
            #pragma unroll
            for (int j = 0; j < 8; j++) {
                s[j][0] = exp2f(fmaf(s[j][0], kl, nb0));
                s[j][1] = exp2f(fmaf(s[j][1], kl, nb0));
                s[j][2] = exp2f(fmaf(s[j][2], kl, nb1));
                s[j][3] = exp2f(fmaf(s[j][3], kl, nb1));
                sum0 += s[j][0] + s[j][1];
                sum1 += s[j][2] + s[j][3];
            }
            sum0 += __shfl_xor_sync(0xFFFFFFFFu, sum0, 1);
            sum0 += __shfl_xor_sync(0xFFFFFFFFu, sum0, 2);
            sum1 += __shfl_xor_sync(0xFFFFFFFFu, sum1, 1);
            sum1 += __shfl_xor_sync(0xFFFFFFFFu, sum1, 2);
            l0 = l0 * corr0 + sum0;
            l1 = l1 * corr1 + sum1;
            m0 = nm0; m1 = nm1;
            #pragma unroll
            for (int n = 0; n < 16; n++) {
                acc_o[n][0] *= corr0; acc_o[n][1] *= corr0;
                acc_o[n][2] *= corr1; acc_o[n][3] *= corr1;
            }

            uint32_t aP[4][4];
            #pragma unroll
            for (int g = 0; g < 4; ++g) {
                #pragma unroll
                for (int part = 0; part < 4; ++part) {
                    const int j = 2 * g + (part >> 1);
                    const int e = (part & 1) * 2;
                    aP[g][part] = packh2(s[j][e], s[j][e + 1]);
                }
            }

            #pragma unroll
            for (int n16 = 0; n16 < 8; ++n16) {
                #pragma unroll
                for (int kk = 0; kk < 4; ++kk) {
                    uint32_t vf[4];
                    LDSM4T(vf, stg + VOFF + (uint32_t)(kk * 16) * FROWB + voffBase + n16 * 32);
                    MMAH(acc_o[2*n16],   aP[kk], vf[0], vf[1]);
                    MMAH(acc_o[2*n16+1], aP[kk], vf[2], vf[3]);
                }
            }
        }
    }

    const float inv0 = 1.f / l0, inv1 = 1.f / l1;
    #pragma unroll
    for (int n8 = 0; n8 < 16; ++n8) {
        const int col = h * HD + n8 * 8 + (lane & 3) * 2;
        *(uint32_t*)&oh[(size_t)r0g * DIM + col] =
            packh2(acc_o[n8][0] * inv0, acc_o[n8][1] * inv0);
        *(uint32_t*)&oh[(size_t)(r0g + 8) * DIM + col] =
            packh2(acc_o[n8][2] * inv1, acc_o[n8][3] * inv1);
    }
}

// ---------------------------------------------------------------------------
extern "C" void kernel_launch(void* const* d_in, const int* in_sizes, int n_in,
                              void* d_out, int out_size)
{
    const float* x    = (const float*)d_in[0];
    const float* fc   = (const float*)d_in[1];
    const float* fs   = (const float*)d_in[2];
    const float* wk_w = (const float*)d_in[6];
    const float* wk_b = (const float*)d_in[7];
    const float* wv_w = (const float*)d_in[8];
    const float* wv_b = (const float*)d_in[9];
    const float* wo_w = (const float*)d_in[10];
    const float* wo_b = (const float*)d_in[11];
    float* out = (float*)d_out;

    __half *xh, *woh, *wkh, *wvh, *qh, *kh, *vh, *ah;
    cudaGetSymbolAddress((void**)&xh,  g_xh);
    cudaGetSymbolAddress((void**)&woh, g_woh);
    cudaGetSymbolAddress((void**)&wkh, g_wkh);
    cudaGetSymbolAddress((void**)&wvh, g_wvh);
    cudaGetSymbolAddress((void**)&qh,  g_qh);
    cudaGetSymbolAddress((void**)&kh,  g_kh);
    cudaGetSymbolAddress((void**)&vh,  g_vh);
    cudaGetSymbolAddress((void**)&ah,  g_ah);

    // 0) merged fp32 -> fp16 converts (MLP=8)
    cvt_all_kernel<<<4096, 256>>>(x, wo_w, wk_w, wv_w, xh, woh, wkh, wvh);

    cudaFuncSetAttribute(qkv_gemm_kernel,
                         cudaFuncAttributeMaxDynamicSharedMemorySize, GSMEM);
    cudaFuncSetAttribute(out_gemm_kernel,
                         cudaFuncAttributeMaxDynamicSharedMemorySize, GSMEM);
    cudaFuncSetAttribute(fa_mma_kernel,
                         cudaFuncAttributeMaxDynamicSharedMemorySize, FA2SMEM);

    // 1) fused QKV projection + bias + RoPE -> fp16 q/k/v
    dim3 gqkv(48, 16);
    qkv_gemm_kernel<<<gqkv, 256, GSMEM>>>(xh,
                                          woh, wo_b, qh,
                                          wkh, wk_b, kh,
                                          wvh, wv_b, vh,
                                          fc, fs);

    // 2) fp16 tensor-core causal GQA flash attention -> fp16 att (2 CTAs/SM)
    dim3 gfa(T_SEQ / 128, NH);
    fa_mma_kernel<<<gfa, 256, FA2SMEM>>>(qh, kh, vh, ah);

    // 3) output projection -> fp32 out
    dim3 go(32, 16);
    out_gemm_kernel<<<go, 256, GSMEM>>>(ah, woh, wo_b, out);
}